// round 11
// baseline (speedup 1.0000x reference)
#include <cuda_runtime.h>

#define SEQ    2048
#define DIM    4096
#define BATCH  4
#define PAD_ID 50256
#define NROWS  (2 * BATCH * SEQ)     // 16384
#define TPB    256                   // 8 warps/block, 8 rows/block
#define NBLK   (NROWS / 8)           // 2048 blocks

__device__ unsigned int g_counter = 0;   // arrival tickets
__device__ unsigned int g_fin     = 0;   // stats-finisher count
__device__ int          g_div[BATCH];
__device__ int          g_end[BATCH];
__device__ __align__(16) float g_rew[NROWS];   // aligned mirror of rewards

// ---------------------------------------------------------------------------
// Fused kernel: [blocks 0-3: div/end pre-pass] + matvec + [last 4: stats tail]
// Calibrated operating point: 80 regs, 3 CTAs/SM (24 warps), full-unroll
// front-batched loads. This is the LTS-cap floor (~11.6 TB/s delivered).
// ---------------------------------------------------------------------------
__global__ void __launch_bounds__(TPB, 2)
reward_fused_kernel(const float* __restrict__ hs,
                    const float* __restrict__ w,
                    const int*   __restrict__ ids,
                    float*       __restrict__ out) {
    float* rewards = out + 1;                       // [2B*S] (4-byte aligned only)
    const int tid  = threadIdx.x;
    const int lane = tid & 31;
    const int warp = tid >> 5;

    __shared__ int   sh_min[3];
    __shared__ float sh_c[8], sh_r[8], sh_l[8];
    __shared__ int   sh_n[8];
    __shared__ unsigned int sh_ticket;

    // ---- pre-pass: blocks 0..BATCH-1 compute div/end for their pair ----
    if (blockIdx.x < BATCH) {
        const int pb = blockIdx.x;
        if (tid < 3) sh_min[tid] = SEQ;
        __syncthreads();
        const int4* cid4 = reinterpret_cast<const int4*>(ids + (size_t)pb * SEQ);
        const int4* rid4 = reinterpret_cast<const int4*>(ids + (size_t)(pb + BATCH) * SEQ);
        int dloc = SEQ, cloc = SEQ, rloc = SEQ;
        for (int i = tid; i < SEQ / 4; i += TPB) {
            int4 c = cid4[i];
            int4 r = rid4[i];
            int s = i * 4;
            if (c.x != r.x)    dloc = min(dloc, s + 0);
            if (c.y != r.y)    dloc = min(dloc, s + 1);
            if (c.z != r.z)    dloc = min(dloc, s + 2);
            if (c.w != r.w)    dloc = min(dloc, s + 3);
            if (c.x == PAD_ID) cloc = min(cloc, s + 0);
            if (c.y == PAD_ID) cloc = min(cloc, s + 1);
            if (c.z == PAD_ID) cloc = min(cloc, s + 2);
            if (c.w == PAD_ID) cloc = min(cloc, s + 3);
            if (r.x == PAD_ID) rloc = min(rloc, s + 0);
            if (r.y == PAD_ID) rloc = min(rloc, s + 1);
            if (r.z == PAD_ID) rloc = min(rloc, s + 2);
            if (r.w == PAD_ID) rloc = min(rloc, s + 3);
        }
        atomicMin(&sh_min[0], dloc);
        atomicMin(&sh_min[1], cloc);
        atomicMin(&sh_min[2], rloc);
        __syncthreads();
        if (tid == 0) {
            g_div[pb] = sh_min[0];
            g_end[pb] = max(sh_min[1], sh_min[2]);
            if (pb == 0) out[0] = 0.0f;             // zero loss slot
        }
        __syncthreads();
    }

    // ---- matvec: one warp per row, fully unrolled (ptxas front-batches) ----
    {
        int gwarp = blockIdx.x * (TPB / 32) + warp;
        const float4* row = reinterpret_cast<const float4*>(hs + (size_t)gwarp * DIM) + lane;
        const float4* w4  = reinterpret_cast<const float4*>(w) + lane;
        float acc0 = 0.0f, acc1 = 0.0f;
        #pragma unroll
        for (int i = 0; i < DIM / 4 / 32; i += 2) {
            float4 a0 = __ldg(row + (i + 0) * 32);
            float4 a1 = __ldg(row + (i + 1) * 32);
            float4 b0 = __ldg(w4  + (i + 0) * 32);
            float4 b1 = __ldg(w4  + (i + 1) * 32);
            acc0 = fmaf(a0.x, b0.x, acc0);
            acc0 = fmaf(a0.y, b0.y, acc0);
            acc0 = fmaf(a0.z, b0.z, acc0);
            acc0 = fmaf(a0.w, b0.w, acc0);
            acc1 = fmaf(a1.x, b1.x, acc1);
            acc1 = fmaf(a1.y, b1.y, acc1);
            acc1 = fmaf(a1.z, b1.z, acc1);
            acc1 = fmaf(a1.w, b1.w, acc1);
        }
        float acc = acc0 + acc1;
        #pragma unroll
        for (int off = 16; off > 0; off >>= 1)
            acc += __shfl_xor_sync(0xffffffffu, acc, off);
        if (lane == 0) {
            rewards[gwarp] = acc;
            g_rew[gwarp]   = acc;
        }
    }

    // ---- arrival ticket (publish rewards first) ----
    __syncthreads();
    if (tid == 0) {
        __threadfence();
        sh_ticket = atomicAdd(&g_counter, 1u);
    }
    __syncthreads();
    const unsigned int ticket = sh_ticket;
    if (ticket < (unsigned)NBLK - BATCH) return;

    // ---- wait for ALL blocks to publish (no ticket race) ----
    if (tid == 0) {
        volatile unsigned int* vc = &g_counter;
        while (*vc < (unsigned)NBLK) { /* spin */ }
        __threadfence();
    }
    __syncthreads();

    // ---- stats tail: this block owns pair b ----
    const int b = NBLK - 1 - (int)ticket;           // 0..BATCH-1
    const int div_i = g_div[b];
    const int end_i = g_end[b];

    // masked sums — float4 on aligned, L2-hot g_rew
    float sc = 0.0f, sr = 0.0f, sl = 0.0f;
    int   cnt = 0;
    {
        const float4* cr4 = reinterpret_cast<const float4*>(g_rew + (size_t)b * SEQ);
        const float4* rr4 = reinterpret_cast<const float4*>(g_rew + (size_t)(b + BATCH) * SEQ);
        for (int i = tid; i < SEQ / 4; i += TPB) {
            float4 c = cr4[i];
            float4 r = rr4[i];
            int s = i * 4;
            #pragma unroll
            for (int j = 0; j < 4; j++) {
                float cv = (j == 0) ? c.x : (j == 1) ? c.y : (j == 2) ? c.z : c.w;
                float rv = (j == 0) ? r.x : (j == 1) ? r.y : (j == 2) ? r.z : r.w;
                int   ss = s + j;
                if (ss >= div_i && ss < end_i) {
                    sc += cv;
                    sr += rv;
                    float x = cv - rv;
                    sl += fmaxf(-x, 0.0f) + log1pf(expf(-fabsf(x)));
                    cnt++;
                }
            }
        }
    }
    #pragma unroll
    for (int off = 16; off > 0; off >>= 1) {
        sc  += __shfl_xor_sync(0xffffffffu, sc,  off);
        sr  += __shfl_xor_sync(0xffffffffu, sr,  off);
        sl  += __shfl_xor_sync(0xffffffffu, sl,  off);
        cnt += __shfl_xor_sync(0xffffffffu, cnt, off);
    }
    if (lane == 0) { sh_c[warp] = sc; sh_r[warp] = sr; sh_l[warp] = sl; sh_n[warp] = cnt; }
    __syncthreads();

    if (tid == 0) {
        float c0 = 0.0f, r0 = 0.0f, l0 = 0.0f;
        int   n0 = 0;
        #pragma unroll
        for (int k = 0; k < 8; k++) { c0 += sh_c[k]; r0 += sh_r[k]; l0 += sh_l[k]; n0 += sh_n[k]; }

        float* out_cm = out + 1 + NROWS;            // chosen_mean[4]
        float* out_rm = out_cm + BATCH;             // rejected_mean[4]
        float* out_ce = out_rm + BATCH;             // chosen_end[4]
        float* out_re = out_ce + BATCH;             // rejected_end[4]
        float fcnt = fmaxf((float)n0, 1.0f);
        out_cm[b] = c0 / fcnt;
        out_rm[b] = r0 / fcnt;
        int last = max(end_i - 1, 0);
        out_ce[b] = g_rew[(size_t)b * SEQ + last];
        out_re[b] = g_rew[(size_t)(b + BATCH) * SEQ + last];
        atomicAdd(out, l0 / fcnt * (1.0f / (float)BATCH));

        // finisher accounting: last stats block resets counters for next replay
        unsigned int f = atomicAdd(&g_fin, 1u);
        if (f == BATCH - 1u) {
            atomicExch(&g_counter, 0u);
            atomicExch(&g_fin, 0u);
        }
    }
}

// ---------------------------------------------------------------------------
extern "C" void kernel_launch(void* const* d_in, const int* in_sizes, int n_in,
                              void* d_out, int out_size) {
    const float* hs  = (const float*)d_in[0];       // (2B, S, D) fp32
    const float* w   = (const float*)d_in[1];       // (D,) fp32
    const int*   ids = (const int*)d_in[2];         // (2B, S) int32

    reward_fused_kernel<<<NBLK, TPB>>>(hs, w, ids, (float*)d_out);
}

// round 12
// speedup vs baseline: 1.0874x; 1.0874x over previous
#include <cuda_runtime.h>

#define SEQ    2048
#define DIM    4096
#define BATCH  4
#define PAD_ID 50256
#define NROWS  (2 * BATCH * SEQ)     // 16384
#define TPB    256                   // 8 warps/block, 8 rows/block
#define NBLK   (NROWS / 8)           // 2048 blocks

__device__ unsigned int g_counter = 0;   // arrival tickets
__device__ unsigned int g_fin     = 0;   // stats-finisher count
__device__ int          g_div[BATCH];
__device__ int          g_end[BATCH];
__device__ __align__(16) float g_rew[NROWS];   // aligned mirror of rewards

// ---------------------------------------------------------------------------
// Fused kernel: [blocks 0-3: div/end pre-pass] + matvec + [last 4: stats tail]
// Calibrated: launch_bounds(256,1) -> ptxas picks 80 regs, 3 CTAs/SM.
// ---------------------------------------------------------------------------
__global__ void __launch_bounds__(TPB, 1)
reward_fused_kernel(const float* __restrict__ hs,
                    const float* __restrict__ w,
                    const int*   __restrict__ ids,
                    float*       __restrict__ out) {
    float* rewards = out + 1;                       // [2B*S] (4-byte aligned only)
    const int tid  = threadIdx.x;
    const int lane = tid & 31;
    const int warp = tid >> 5;

    __shared__ int   sh_min[3];
    __shared__ float sh_c[8], sh_r[8], sh_l[8];
    __shared__ int   sh_n[8];
    __shared__ unsigned int sh_ticket;

    // ---- pre-pass: blocks 0..BATCH-1 compute div/end for their pair ----
    if (blockIdx.x < BATCH) {
        const int pb = blockIdx.x;
        if (tid < 3) sh_min[tid] = SEQ;
        __syncthreads();
        const int4* cid4 = reinterpret_cast<const int4*>(ids + (size_t)pb * SEQ);
        const int4* rid4 = reinterpret_cast<const int4*>(ids + (size_t)(pb + BATCH) * SEQ);
        int dloc = SEQ, cloc = SEQ, rloc = SEQ;
        for (int i = tid; i < SEQ / 4; i += TPB) {
            int4 c = cid4[i];
            int4 r = rid4[i];
            int s = i * 4;
            if (c.x != r.x)    dloc = min(dloc, s + 0);
            if (c.y != r.y)    dloc = min(dloc, s + 1);
            if (c.z != r.z)    dloc = min(dloc, s + 2);
            if (c.w != r.w)    dloc = min(dloc, s + 3);
            if (c.x == PAD_ID) cloc = min(cloc, s + 0);
            if (c.y == PAD_ID) cloc = min(cloc, s + 1);
            if (c.z == PAD_ID) cloc = min(cloc, s + 2);
            if (c.w == PAD_ID) cloc = min(cloc, s + 3);
            if (r.x == PAD_ID) rloc = min(rloc, s + 0);
            if (r.y == PAD_ID) rloc = min(rloc, s + 1);
            if (r.z == PAD_ID) rloc = min(rloc, s + 2);
            if (r.w == PAD_ID) rloc = min(rloc, s + 3);
        }
        atomicMin(&sh_min[0], dloc);
        atomicMin(&sh_min[1], cloc);
        atomicMin(&sh_min[2], rloc);
        __syncthreads();
        if (tid == 0) {
            g_div[pb] = sh_min[0];
            g_end[pb] = max(sh_min[1], sh_min[2]);
            if (pb == 0) out[0] = 0.0f;             // zero loss slot
        }
        __syncthreads();
    }

    // ---- matvec: one warp per row (deep per-warp MLP, 80-reg schedule) ----
    {
        int gwarp = blockIdx.x * (TPB / 32) + warp;
        const float4* row = reinterpret_cast<const float4*>(hs + (size_t)gwarp * DIM);
        const float4* w4  = reinterpret_cast<const float4*>(w);
        float acc = 0.0f;
        #pragma unroll 8
        for (int i = lane; i < DIM / 4; i += 32) {
            float4 a = __ldg(&row[i]);
            float4 b = __ldg(&w4[i]);
            acc = fmaf(a.x, b.x, acc);
            acc = fmaf(a.y, b.y, acc);
            acc = fmaf(a.z, b.z, acc);
            acc = fmaf(a.w, b.w, acc);
        }
        #pragma unroll
        for (int off = 16; off > 0; off >>= 1)
            acc += __shfl_xor_sync(0xffffffffu, acc, off);
        if (lane == 0) {
            rewards[gwarp] = acc;
            g_rew[gwarp]   = acc;
        }
    }

    // ---- arrival ticket (publish rewards first) ----
    __syncthreads();
    if (tid == 0) {
        __threadfence();
        sh_ticket = atomicAdd(&g_counter, 1u);
    }
    __syncthreads();
    const unsigned int ticket = sh_ticket;
    if (ticket < (unsigned)NBLK - BATCH) return;

    // ---- wait for ALL blocks to publish (no ticket race) ----
    if (tid == 0) {
        volatile unsigned int* vc = &g_counter;
        while (*vc < (unsigned)NBLK) { /* spin */ }
        __threadfence();
    }
    __syncthreads();

    // ---- stats tail: this block owns pair b ----
    const int b = NBLK - 1 - (int)ticket;           // 0..BATCH-1
    const int div_i = g_div[b];
    const int end_i = g_end[b];

    // masked sums — float4 on aligned, L2-hot g_rew
    float sc = 0.0f, sr = 0.0f, sl = 0.0f;
    int   cnt = 0;
    {
        const float4* cr4 = reinterpret_cast<const float4*>(g_rew + (size_t)b * SEQ);
        const float4* rr4 = reinterpret_cast<const float4*>(g_rew + (size_t)(b + BATCH) * SEQ);
        for (int i = tid; i < SEQ / 4; i += TPB) {
            float4 c = cr4[i];
            float4 r = rr4[i];
            int s = i * 4;
            #pragma unroll
            for (int j = 0; j < 4; j++) {
                float cv = (j == 0) ? c.x : (j == 1) ? c.y : (j == 2) ? c.z : c.w;
                float rv = (j == 0) ? r.x : (j == 1) ? r.y : (j == 2) ? r.z : r.w;
                int   ss = s + j;
                if (ss >= div_i && ss < end_i) {
                    sc += cv;
                    sr += rv;
                    float x = cv - rv;
                    sl += fmaxf(-x, 0.0f) + log1pf(expf(-fabsf(x)));
                    cnt++;
                }
            }
        }
    }
    #pragma unroll
    for (int off = 16; off > 0; off >>= 1) {
        sc  += __shfl_xor_sync(0xffffffffu, sc,  off);
        sr  += __shfl_xor_sync(0xffffffffu, sr,  off);
        sl  += __shfl_xor_sync(0xffffffffu, sl,  off);
        cnt += __shfl_xor_sync(0xffffffffu, cnt, off);
    }
    if (lane == 0) { sh_c[warp] = sc; sh_r[warp] = sr; sh_l[warp] = sl; sh_n[warp] = cnt; }
    __syncthreads();

    if (tid == 0) {
        float c0 = 0.0f, r0 = 0.0f, l0 = 0.0f;
        int   n0 = 0;
        #pragma unroll
        for (int k = 0; k < 8; k++) { c0 += sh_c[k]; r0 += sh_r[k]; l0 += sh_l[k]; n0 += sh_n[k]; }

        float* out_cm = out + 1 + NROWS;            // chosen_mean[4]
        float* out_rm = out_cm + BATCH;             // rejected_mean[4]
        float* out_ce = out_rm + BATCH;             // chosen_end[4]
        float* out_re = out_ce + BATCH;             // rejected_end[4]
        float fcnt = fmaxf((float)n0, 1.0f);
        out_cm[b] = c0 / fcnt;
        out_rm[b] = r0 / fcnt;
        int last = max(end_i - 1, 0);
        out_ce[b] = g_rew[(size_t)b * SEQ + last];
        out_re[b] = g_rew[(size_t)(b + BATCH) * SEQ + last];
        atomicAdd(out, l0 / fcnt * (1.0f / (float)BATCH));

        // finisher accounting: last stats block resets counters for next replay
        unsigned int f = atomicAdd(&g_fin, 1u);
        if (f == BATCH - 1u) {
            atomicExch(&g_counter, 0u);
            atomicExch(&g_fin, 0u);
        }
    }
}

// ---------------------------------------------------------------------------
extern "C" void kernel_launch(void* const* d_in, const int* in_sizes, int n_in,
                              void* d_out, int out_size) {
    const float* hs  = (const float*)d_in[0];       // (2B, S, D) fp32
    const float* w   = (const float*)d_in[1];       // (D,) fp32
    const int*   ids = (const int*)d_in[2];         // (2B, S) int32

    reward_fused_kernel<<<NBLK, TPB>>>(hs, w, ids, (float*)d_out);
}